// round 13
// baseline (speedup 1.0000x reference)
#include <cuda_runtime.h>
#include <cuda_fp16.h>
#include <cstdint>
#include <math.h>

// Sizes fixed: B=4, T=2048, E=1024, M=2048; R = B*T = 8192.
#define R_ROWS 8192
#define E_DIM  1024
#define M_DIM  2048
#define NCHUNK 16
#define TCH    128

// ---------------- scratch ----------------
__device__ float g_x2[R_ROWS * E_DIM];
__device__ float g_Ac[NCHUNK * 8192];
__device__ float g_Sc[NCHUNK * 8192];
__device__ float g_Hc[NCHUNK * 8192];
#define WSLOT (E_DIM * M_DIM)
__device__ __align__(256) __half g_wH[8 * WSLOT];      // transposed fp16 weights [N][K]
__device__ __align__(256) __half g_yh[R_ROWS * E_DIM]; // LN1 out
__device__ __align__(256) __half g_zh[R_ROWS * E_DIM]; // LN2 out
__device__ __align__(256) __half g_gh[R_ROWS * M_DIM]; // gate out
__device__ __align__(256) __half g_zi[R_ROWS * M_DIM]; // FFN gated product
__device__ __align__(256) __half g_b0[R_ROWS * M_DIM];
__device__ __align__(256) __half g_b1[R_ROWS * M_DIM];
__device__ __align__(256) __half g_r [R_ROWS * M_DIM];
__device__ __align__(256) __half g_og[R_ROWS * M_DIM];

__device__ __forceinline__ float sigm(float x) { return 1.f / (1.f + __expf(-x)); }

__device__ __forceinline__ uint32_t smem_u32(const void* p) {
    uint32_t a;
    asm("{ .reg .u64 t; cvta.to.shared.u64 t, %1; cvt.u32.u64 %0, t; }" : "=r"(a) : "l"(p));
    return a;
}

#define CP_ASYNC16(dst, src) asm volatile("cp.async.cg.shared.global [%0], [%1], 16;" :: "r"(dst), "l"(src))
#define CP_COMMIT()          asm volatile("cp.async.commit_group;" ::: "memory")
#define CP_WAIT2()           asm volatile("cp.async.wait_group 2;" ::: "memory")

#define LDSM4(r0, r1, r2, r3, addr)                                            \
    asm volatile("ldmatrix.sync.aligned.m8n8.x4.shared.b16 {%0,%1,%2,%3}, [%4];" \
        : "=r"(r0), "=r"(r1), "=r"(r2), "=r"(r3) : "r"(addr))

#define MMA_F16(c, a, b)                                                       \
    asm volatile("mma.sync.aligned.m16n8k16.row.col.f32.f16.f16.f32 "          \
        "{%0,%1,%2,%3}, {%4,%5,%6,%7}, {%8,%9}, {%0,%1,%2,%3};"                \
        : "+f"((c)[0]), "+f"((c)[1]), "+f"((c)[2]), "+f"((c)[3])               \
        : "r"((a)[0]), "r"((a)[1]), "r"((a)[2]), "r"((a)[3]),                  \
          "r"((b)[0]), "r"((b)[1]))

__device__ __forceinline__ uint32_t pack_h2(float a, float b) {
    __half2 h = __floats2half2_rn(a, b);
    return *reinterpret_cast<uint32_t*>(&h);
}

// ---------------- batched fused transpose + fp16 convert ----------------
struct TArgs { const float* s[8]; __half* d[8]; int K[8]; int N[8]; };
__global__ __launch_bounds__(256) void tcvt8(TArgs a) {
    __shared__ float t[32][33];
    int w = blockIdx.y;
    int K = a.K[w], N = a.N[w];
    int nb = N >> 5;
    int bx = (blockIdx.x % nb) * 32;
    int by = (blockIdx.x / nb) * 32;
    const float* src = a.s[w];
    __half* dst = a.d[w];
#pragma unroll
    for (int i = threadIdx.y; i < 32; i += 8)
        t[i][threadIdx.x] = src[(size_t)(by + i) * N + bx + threadIdx.x];
    __syncthreads();
#pragma unroll
    for (int i = threadIdx.y; i < 32; i += 8)
        dst[(size_t)(bx + i) * K + by + threadIdx.x] = __float2half_rn(t[threadIdx.x][i]);
}

// ---------------- LayerNorm (rows of 1024), fp16 output ----------------
__global__ __launch_bounds__(256) void ln1024(const float* __restrict__ x,
                                              const float* __restrict__ w,
                                              const float* __restrict__ b,
                                              __half* __restrict__ y) {
    int row = blockIdx.x;
    const float4* xr = (const float4*)(x + (size_t)row * 1024);
    float4 v = xr[threadIdx.x];
    float s = v.x + v.y + v.z + v.w;
    float q = v.x * v.x + v.y * v.y + v.z * v.z + v.w * v.w;
#pragma unroll
    for (int o = 16; o; o >>= 1) {
        s += __shfl_xor_sync(0xFFFFFFFF, s, o);
        q += __shfl_xor_sync(0xFFFFFFFF, q, o);
    }
    __shared__ float ss[8], sq[8];
    int wid = threadIdx.x >> 5, lane = threadIdx.x & 31;
    if (lane == 0) { ss[wid] = s; sq[wid] = q; }
    __syncthreads();
    s = 0.f; q = 0.f;
#pragma unroll
    for (int i = 0; i < 8; i++) { s += ss[i]; q += sq[i]; }
    float mu  = s * (1.f / 1024.f);
    float var = q * (1.f / 1024.f) - mu * mu;
    float inv = rsqrtf(var + 1e-5f);
    float4 wv = ((const float4*)w)[threadIdx.x];
    float4 bv = ((const float4*)b)[threadIdx.x];
    uint2 pk;
    pk.x = pack_h2((v.x - mu) * inv * wv.x + bv.x, (v.y - mu) * inv * wv.y + bv.y);
    pk.y = pack_h2((v.z - mu) * inv * wv.z + bv.z, (v.w - mu) * inv * wv.w + bv.w);
    ((uint2*)(y + (size_t)row * 1024))[threadIdx.x] = pk;
}

// ---------------- fp16 mma GEMM: CTA 128x256, BK=32(halves), 6 stages ----------------
// Barrier every 2 K-tiles -> more warp skew, better tensor/SMEM overlap.
// mode 0: raw -> fp16   1: sigmoid(acc+bias) -> fp16   3: acc(+bias)+resid -> fp32
#define NSTG  6
#define ASTH  40
#define AWRDH (128 * ASTH)
#define BWRDH (256 * ASTH)
#define STGH  (AWRDH + BWRDH)
#define GSMEM (NSTG * STGH * 2)     // 184320 bytes

struct GB { const __half* Bt; const float* bias; const float* resid; void* C; int mode; };
struct GArgs { GB g[4]; };

__global__ __launch_bounds__(512, 1) void gemm_mma(const __half* __restrict__ A,
                                                   GArgs ga, int K, int N) {
    extern __shared__ char smem[];
    uint32_t sbase = smem_u32(smem);

    GB gb = ga.g[blockIdx.z];
    const __half* __restrict__ Bt = gb.Bt;

    int tid = threadIdx.x;
    int wid = tid >> 5, lane = tid & 31;
    int wm = wid & 3, wn = wid >> 2;
    int m0 = wm * 32, n0 = wn * 64;
    int grp = lane >> 2, ktid = lane & 3;
    int brow = blockIdx.y * 128, bcol = blockIdx.x * 256;

    int arow = tid >> 2, ach = tid & 3;
    const __half* gA = A + (size_t)(brow + arow) * K + ach * 8;
    uint32_t dA = sbase + (uint32_t)(arow * ASTH + ach * 8) * 2;
    int brw = tid >> 1, bch = tid & 1;
    const __half* gB = Bt + (size_t)(bcol + brw) * K + bch * 16;
    uint32_t dB = sbase + (uint32_t)(AWRDH + brw * ASTH + bch * 16) * 2;

    int l7 = lane & 7;
    int aq = (lane >> 3) & 1, ah = lane >> 4;
    int bq = lane >> 4, bh = (lane >> 3) & 1;
    uint32_t aB = sbase + (uint32_t)((m0 + aq * 8 + l7) * ASTH) * 2 + (uint32_t)(ah * 16);
    uint32_t bB = sbase + (uint32_t)(AWRDH + (n0 + bq * 8 + l7) * ASTH) * 2 + (uint32_t)(bh * 16);

    float acc[2][8][4];
#pragma unroll
    for (int i = 0; i < 2; i++)
#pragma unroll
        for (int j = 0; j < 8; j++)
#pragma unroll
            for (int v = 0; v < 4; v++) acc[i][j][v] = 0.f;

    const int nk = K / 32;   // always even here (32 or 64)

    // prologue: fill 4 stages (one commit each)
#pragma unroll
    for (int p = 0; p < 4; p++) {
        uint32_t o = (uint32_t)p * (STGH * 2);
        CP_ASYNC16(dA + o, gA + p * 32);
        CP_ASYNC16(dB + o, gB + p * 32);
        CP_ASYNC16(dB + o + 16, gB + p * 32 + 8);
        CP_COMMIT();
    }

    int s4 = 4, s5 = 5;   // slots to fill next (kt+4, kt+5)
    for (int kt = 0; kt < nk; kt += 2) {
        CP_WAIT2();            // slots kt, kt+1 resident
        __syncthreads();       // all warps done reading slots being overwritten

        // issue loads for kt+4 and kt+5
        if (kt + 4 < nk) {
            uint32_t o = (uint32_t)s4 * (STGH * 2);
            const __half* a = gA + (kt + 4) * 32;
            const __half* b = gB + (kt + 4) * 32;
            CP_ASYNC16(dA + o, a);
            CP_ASYNC16(dB + o, b);
            CP_ASYNC16(dB + o + 16, b + 8);
        }
        CP_COMMIT();
        if (kt + 5 < nk) {
            uint32_t o = (uint32_t)s5 * (STGH * 2);
            const __half* a = gA + (kt + 5) * 32;
            const __half* b = gB + (kt + 5) * 32;
            CP_ASYNC16(dA + o, a);
            CP_ASYNC16(dB + o, b);
            CP_ASYNC16(dB + o + 16, b + 8);
        }
        CP_COMMIT();
        s4 += 2; if (s4 >= NSTG) s4 -= NSTG;
        s5 += 2; if (s5 >= NSTG) s5 -= NSTG;

        // compute K-tiles kt and kt+1 (slots cycle mod 6)
        int slot = kt % NSTG;
#pragma unroll
        for (int sub = 0; sub < 2; sub++) {
            uint32_t so = (uint32_t)slot * (STGH * 2);
#pragma unroll
            for (int ks = 0; ks < 2; ks++) {
                uint32_t af[2][4], bf[8][2];
#pragma unroll
                for (int mi = 0; mi < 2; mi++)
                    LDSM4(af[mi][0], af[mi][1], af[mi][2], af[mi][3],
                          aB + so + (uint32_t)(mi * 16 * ASTH * 2) + (uint32_t)(ks * 32));
#pragma unroll
                for (int p = 0; p < 4; p++)
                    LDSM4(bf[2 * p][0], bf[2 * p][1], bf[2 * p + 1][0], bf[2 * p + 1][1],
                          bB + so + (uint32_t)(p * 16 * ASTH * 2) + (uint32_t)(ks * 32));
#pragma unroll
                for (int mi = 0; mi < 2; mi++)
#pragma unroll
                    for (int ni = 0; ni < 8; ni++)
                        MMA_F16(acc[mi][ni], af[mi], bf[ni]);
            }
            slot++; if (slot >= NSTG) slot -= NSTG;
        }
    }

    // ---------------- epilogue ----------------
    int mode = gb.mode;
    const float* bias = gb.bias;
    const float* resid = gb.resid;
#pragma unroll
    for (int mi = 0; mi < 2; mi++) {
#pragma unroll
        for (int ni = 0; ni < 8; ni++) {
            int row = brow + m0 + mi * 16 + grp;
            int col = bcol + n0 + ni * 8 + ktid * 2;
            float b0v = 0.f, b1v = 0.f;
            if ((mode != 0) && bias) { b0v = bias[col]; b1v = bias[col + 1]; }
#pragma unroll
            for (int half = 0; half < 2; half++) {
                int r = row + half * 8;
                float v0 = acc[mi][ni][half * 2 + 0] + b0v;
                float v1 = acc[mi][ni][half * 2 + 1] + b1v;
                size_t off = (size_t)r * N + col;
                if (mode == 3) {
                    float2 rr = *(const float2*)(resid + off);
                    float2 o; o.x = v0 + rr.x; o.y = v1 + rr.y;
                    *(float2*)((float*)gb.C + off) = o;
                } else {
                    if (mode == 1) { v0 = sigm(v0); v1 = sigm(v1); }
                    uint32_t pk = pack_h2(v0, v1);
                    *(uint32_t*)((__half*)gb.C + off) = pk;
                }
            }
        }
    }
}

// ---------------- zi = fp16(b0 * b1) elementwise (half in/out) ----------------
__global__ __launch_bounds__(256) void gateprod(const __half2* __restrict__ b0,
                                                const __half2* __restrict__ b1,
                                                __half2* __restrict__ o) {
    int i = blockIdx.x * 256 + threadIdx.x;
    uint2 pa = ((const uint2*)b0)[i];
    uint2 pb = ((const uint2*)b1)[i];
    float2 a0 = __half22float2(*(__half2*)&pa.x), a1 = __half22float2(*(__half2*)&pa.y);
    float2 c0 = __half22float2(*(__half2*)&pb.x), c1 = __half22float2(*(__half2*)&pb.y);
    uint2 pk;
    pk.x = pack_h2(a0.x * c0.x, a0.y * c0.y);
    pk.y = pack_h2(a1.x * c1.x, a1.y * c1.y);
    ((uint2*)o)[i] = pk;
}

// ---------------- chunked scan, half2: 2 adjacent channels / thread ----------------
// pair p = 0..4095 over (b, m/2); channels ch = 2p, 2p+1.
__global__ __launch_bounds__(256) void scan_pass1(const __half2* __restrict__ b0,
                                                  const __half2* __restrict__ b1,
                                                  const __half2* __restrict__ rb,
                                                  float2* __restrict__ Ac,
                                                  float2* __restrict__ Sc) {
    int idx = blockIdx.x * 256 + threadIdx.x;   // c*4096 + p
    int p   = idx & 4095;
    int c   = idx >> 12;
    int b   = p >> 10;
    int base = (b * 2048 + c * TCH) * 1024 + (p & 1023);   // half2 units
    float2 A = make_float2(1.f, 1.f), S = make_float2(0.f, 0.f);
#pragma unroll 4
    for (int t = 0; t < TCH; t++) {
        float2 rr = __half22float2(rb[base]);
        float2 y0 = __half22float2(b0[base]);
        float2 y1 = __half22float2(b1[base]);
        S.x = fmaf(rr.x, S.x, y0.x * y1.x);
        S.y = fmaf(rr.y, S.y, y0.y * y1.y);
        A.x *= rr.x; A.y *= rr.y;
        base += 1024;
    }
    Ac[idx] = A;
    Sc[idx] = S;
}

__global__ __launch_bounds__(256) void scan_pass2(const float* __restrict__ mem,
                                                  const float* __restrict__ Ac,
                                                  const float* __restrict__ Sc,
                                                  float* __restrict__ Hc,
                                                  float* __restrict__ memout) {
    int ch = blockIdx.x * 256 + threadIdx.x;
    float h = mem[ch];
#pragma unroll
    for (int c = 0; c < NCHUNK; c++) {
        int i = c * 8192 + ch;
        Hc[i] = h;
        h = fmaf(Ac[i], h, Sc[i]);
    }
    memout[ch] = h;
}

__global__ __launch_bounds__(256) void scan_pass3(const __half2* __restrict__ b0,
                                                  const __half2* __restrict__ b1,
                                                  const __half2* __restrict__ rb,
                                                  const __half2* __restrict__ og,
                                                  const float2* __restrict__ Hc,
                                                  __half2* __restrict__ g) {
    int idx = blockIdx.x * 256 + threadIdx.x;
    int p   = idx & 4095;
    int c   = idx >> 12;
    int b   = p >> 10;
    int base = (b * 2048 + c * TCH) * 1024 + (p & 1023);
    float2 h = Hc[idx];
#pragma unroll 4
    for (int t = 0; t < TCH; t++) {
        float2 rr = __half22float2(rb[base]);
        float2 y0 = __half22float2(b0[base]);
        float2 y1 = __half22float2(b1[base]);
        h.x = fmaf(rr.x, h.x, y0.x * y1.x);
        h.y = fmaf(rr.y, h.y, y0.y * y1.y);
        float2 o = __half22float2(og[base]);
        float sx = h.x / (1.f + fabsf(h.x));
        float sy = h.y / (1.f + fabsf(h.y));
        uint32_t pk = pack_h2(sx * o.x, sy * o.y);
        g[base] = *(__half2*)&pk;
        base += 1024;
    }
}

// ---------------- host launch ----------------
extern "C" void kernel_launch(void* const* d_in, const int* in_sizes, int n_in,
                              void* d_out, int out_size) {
    const float* x    = (const float*)d_in[0];
    const float* mem  = (const float*)d_in[1];
    const float* ln1w = (const float*)d_in[2];
    const float* ln1b = (const float*)d_in[3];
    const float* wf   = (const float*)d_in[4];
    const float* wfb  = (const float*)d_in[5];
    const float* wi   = (const float*)d_in[6];
    const float* wig  = (const float*)d_in[7];
    const float* wigb = (const float*)d_in[8];
    const float* wog  = (const float*)d_in[9];
    const float* wogb = (const float*)d_in[10];
    const float* wo   = (const float*)d_in[11];
    const float* ln2w = (const float*)d_in[12];
    const float* ln2b = (const float*)d_in[13];
    const float* fwi  = (const float*)d_in[14];
    const float* fwg  = (const float*)d_in[15];
    const float* fwgb = (const float*)d_in[16];
    const float* fwo  = (const float*)d_in[17];
    const float* fwob = (const float*)d_in[18];
    float* out = (float*)d_out;

    float *x2, *Ac, *Sc, *Hc;
    __half *wH, *yh, *zh, *gh, *zi, *b0h, *b1h, *rbh, *ogh;
    cudaGetSymbolAddress((void**)&x2, g_x2);
    cudaGetSymbolAddress((void**)&Ac, g_Ac);
    cudaGetSymbolAddress((void**)&Sc, g_Sc);
    cudaGetSymbolAddress((void**)&Hc, g_Hc);
    cudaGetSymbolAddress((void**)&wH, g_wH);
    cudaGetSymbolAddress((void**)&yh, g_yh);
    cudaGetSymbolAddress((void**)&zh, g_zh);
    cudaGetSymbolAddress((void**)&gh, g_gh);
    cudaGetSymbolAddress((void**)&zi, g_zi);
    cudaGetSymbolAddress((void**)&b0h, g_b0);
    cudaGetSymbolAddress((void**)&b1h, g_b1);
    cudaGetSymbolAddress((void**)&rbh, g_r);
    cudaGetSymbolAddress((void**)&ogh, g_og);

    cudaFuncSetAttribute(gemm_mma, cudaFuncAttributeMaxDynamicSharedMemorySize, GSMEM);

    __half* wiT  = wH + 0 * WSLOT;
    __half* wigT = wH + 1 * WSLOT;
    __half* wfT  = wH + 2 * WSLOT;
    __half* wogT = wH + 3 * WSLOT;
    __half* woT  = wH + 4 * WSLOT;
    __half* fwiT = wH + 5 * WSLOT;
    __half* fwgT = wH + 6 * WSLOT;
    __half* fwoT = wH + 7 * WSLOT;

    TArgs ta;
    ta.s[0] = wi;  ta.d[0] = wiT;  ta.K[0] = E_DIM; ta.N[0] = M_DIM;
    ta.s[1] = wig; ta.d[1] = wigT; ta.K[1] = E_DIM; ta.N[1] = M_DIM;
    ta.s[2] = wf;  ta.d[2] = wfT;  ta.K[2] = E_DIM; ta.N[2] = M_DIM;
    ta.s[3] = wog; ta.d[3] = wogT; ta.K[3] = E_DIM; ta.N[3] = M_DIM;
    ta.s[4] = wo;  ta.d[4] = woT;  ta.K[4] = M_DIM; ta.N[4] = E_DIM;
    ta.s[5] = fwi; ta.d[5] = fwiT; ta.K[5] = E_DIM; ta.N[5] = M_DIM;
    ta.s[6] = fwg; ta.d[6] = fwgT; ta.K[6] = E_DIM; ta.N[6] = M_DIM;
    ta.s[7] = fwo; ta.d[7] = fwoT; ta.K[7] = M_DIM; ta.N[7] = E_DIM;
    dim3 tg(WSLOT / (32 * 32), 8);
    tcvt8<<<tg, dim3(32, 8)>>>(ta);

    ln1024<<<R_ROWS, 256>>>(x, ln1w, ln1b, yh);

    // 4 gate GEMMs in one launch (fp16 outputs)
    {
        GArgs ga;
        ga.g[0] = { wiT,  nullptr, nullptr, b0h, 0 };
        ga.g[1] = { wigT, wigb,    nullptr, b1h, 1 };
        ga.g[2] = { wfT,  wfb,     nullptr, rbh, 1 };
        ga.g[3] = { wogT, wogb,    nullptr, ogh, 1 };
        dim3 gr(M_DIM / 256, R_ROWS / 128, 4);
        gemm_mma<<<gr, 512, GSMEM>>>(yh, ga, E_DIM, M_DIM);
    }

    scan_pass1<<<NCHUNK * 4096 / 256, 256>>>((const __half2*)b0h, (const __half2*)b1h,
                                             (const __half2*)rbh, (float2*)Ac, (float2*)Sc);
    scan_pass2<<<8192 / 256, 256>>>(mem, Ac, Sc, Hc, out + (size_t)R_ROWS * E_DIM);
    scan_pass3<<<NCHUNK * 4096 / 256, 256>>>((const __half2*)b0h, (const __half2*)b1h,
                                             (const __half2*)rbh, (const __half2*)ogh,
                                             (const float2*)Hc, (__half2*)gh);

    // x2 = x + g @ wo
    {
        GArgs ga;
        ga.g[0] = { woT, nullptr, x, x2, 3 };
        dim3 gr(E_DIM / 256, R_ROWS / 128, 1);
        gemm_mma<<<gr, 512, GSMEM>>>(gh, ga, M_DIM, E_DIM);
    }

    ln1024<<<R_ROWS, 256>>>(x2, ln2w, ln2b, zh);

    // FFN in+gate in one launch (fp16 outputs)
    {
        GArgs ga;
        ga.g[0] = { fwiT, nullptr, nullptr, b0h, 0 };
        ga.g[1] = { fwgT, fwgb,    nullptr, b1h, 1 };
        dim3 gr(M_DIM / 256, R_ROWS / 128, 2);
        gemm_mma<<<gr, 512, GSMEM>>>(zh, ga, E_DIM, M_DIM);
    }

    // zi = fp16(b0*b1)
    gateprod<<<R_ROWS * M_DIM / 4 / 256, 256>>>((const __half2*)b0h, (const __half2*)b1h, (__half2*)zi);

    // out = x2 + zi @ fwo + fwob
    {
        GArgs ga;
        ga.g[0] = { fwoT, fwob, x2, out, 3 };
        dim3 gr(E_DIM / 256, R_ROWS / 128, 1);
        gemm_mma<<<gr, 512, GSMEM>>>(zi, ga, M_DIM, E_DIM);
    }
}

// round 14
// speedup vs baseline: 1.0310x; 1.0310x over previous
#include <cuda_runtime.h>
#include <cuda_fp16.h>
#include <cstdint>
#include <math.h>

// Sizes fixed: B=4, T=2048, E=1024, M=2048; R = B*T = 8192.
#define R_ROWS 8192
#define E_DIM  1024
#define M_DIM  2048
#define NCHUNK 16
#define TCH    128

// ---------------- scratch ----------------
__device__ float g_x2[R_ROWS * E_DIM];
__device__ float g_Ac[NCHUNK * 8192];
__device__ float g_Sc[NCHUNK * 8192];
__device__ float g_Hc[NCHUNK * 8192];
#define WSLOT (E_DIM * M_DIM)
__device__ __align__(256) __half g_wH[8 * WSLOT];      // transposed fp16 weights [N][K]
__device__ __align__(256) __half g_yh[R_ROWS * E_DIM]; // LN1 out
__device__ __align__(256) __half g_zh[R_ROWS * E_DIM]; // LN2 out
__device__ __align__(256) __half g_gh[R_ROWS * M_DIM]; // gate out
__device__ __align__(256) __half g_zi[R_ROWS * M_DIM]; // FFN gated product
__device__ __align__(256) __half g_b0[R_ROWS * M_DIM];
__device__ __align__(256) __half g_b1[R_ROWS * M_DIM];
__device__ __align__(256) __half g_r [R_ROWS * M_DIM];
__device__ __align__(256) __half g_og[R_ROWS * M_DIM];

__device__ __forceinline__ float sigm(float x) { return 1.f / (1.f + __expf(-x)); }

__device__ __forceinline__ uint32_t smem_u32(const void* p) {
    uint32_t a;
    asm("{ .reg .u64 t; cvta.to.shared.u64 t, %1; cvt.u32.u64 %0, t; }" : "=r"(a) : "l"(p));
    return a;
}

#define CP_ASYNC16(dst, src) asm volatile("cp.async.cg.shared.global [%0], [%1], 16;" :: "r"(dst), "l"(src))
#define CP_COMMIT()          asm volatile("cp.async.commit_group;" ::: "memory")
#define CP_WAIT3()           asm volatile("cp.async.wait_group 3;" ::: "memory")

#define LDSM4(r0, r1, r2, r3, addr)                                            \
    asm volatile("ldmatrix.sync.aligned.m8n8.x4.shared.b16 {%0,%1,%2,%3}, [%4];" \
        : "=r"(r0), "=r"(r1), "=r"(r2), "=r"(r3) : "r"(addr))

#define MMA_F16(c, a, b)                                                       \
    asm volatile("mma.sync.aligned.m16n8k16.row.col.f32.f16.f16.f32 "          \
        "{%0,%1,%2,%3}, {%4,%5,%6,%7}, {%8,%9}, {%0,%1,%2,%3};"                \
        : "+f"((c)[0]), "+f"((c)[1]), "+f"((c)[2]), "+f"((c)[3])               \
        : "r"((a)[0]), "r"((a)[1]), "r"((a)[2]), "r"((a)[3]),                  \
          "r"((b)[0]), "r"((b)[1]))

__device__ __forceinline__ uint32_t pack_h2(float a, float b) {
    __half2 h = __floats2half2_rn(a, b);
    return *reinterpret_cast<uint32_t*>(&h);
}

// ---------------- batched fused transpose + fp16 convert ----------------
struct TArgs { const float* s[8]; __half* d[8]; int K[8]; int N[8]; };
__global__ __launch_bounds__(256) void tcvt8(TArgs a) {
    __shared__ float t[32][33];
    int w = blockIdx.y;
    int K = a.K[w], N = a.N[w];
    int nb = N >> 5;
    int bx = (blockIdx.x % nb) * 32;
    int by = (blockIdx.x / nb) * 32;
    const float* src = a.s[w];
    __half* dst = a.d[w];
#pragma unroll
    for (int i = threadIdx.y; i < 32; i += 8)
        t[i][threadIdx.x] = src[(size_t)(by + i) * N + bx + threadIdx.x];
    __syncthreads();
#pragma unroll
    for (int i = threadIdx.y; i < 32; i += 8)
        dst[(size_t)(bx + i) * K + by + threadIdx.x] = __float2half_rn(t[threadIdx.x][i]);
}

// ---------------- LayerNorm (rows of 1024), fp16 output ----------------
__global__ __launch_bounds__(256) void ln1024(const float* __restrict__ x,
                                              const float* __restrict__ w,
                                              const float* __restrict__ b,
                                              __half* __restrict__ y) {
    int row = blockIdx.x;
    const float4* xr = (const float4*)(x + (size_t)row * 1024);
    float4 v = xr[threadIdx.x];
    float s = v.x + v.y + v.z + v.w;
    float q = v.x * v.x + v.y * v.y + v.z * v.z + v.w * v.w;
#pragma unroll
    for (int o = 16; o; o >>= 1) {
        s += __shfl_xor_sync(0xFFFFFFFF, s, o);
        q += __shfl_xor_sync(0xFFFFFFFF, q, o);
    }
    __shared__ float ss[8], sq[8];
    int wid = threadIdx.x >> 5, lane = threadIdx.x & 31;
    if (lane == 0) { ss[wid] = s; sq[wid] = q; }
    __syncthreads();
    s = 0.f; q = 0.f;
#pragma unroll
    for (int i = 0; i < 8; i++) { s += ss[i]; q += sq[i]; }
    float mu  = s * (1.f / 1024.f);
    float var = q * (1.f / 1024.f) - mu * mu;
    float inv = rsqrtf(var + 1e-5f);
    float4 wv = ((const float4*)w)[threadIdx.x];
    float4 bv = ((const float4*)b)[threadIdx.x];
    uint2 pk;
    pk.x = pack_h2((v.x - mu) * inv * wv.x + bv.x, (v.y - mu) * inv * wv.y + bv.y);
    pk.y = pack_h2((v.z - mu) * inv * wv.z + bv.z, (v.w - mu) * inv * wv.w + bv.w);
    ((uint2*)(y + (size_t)row * 1024))[threadIdx.x] = pk;
}

// ---------------- fp16 mma GEMM: CTA 128x256, BK=32(halves), 5 stages ----------------
// Barrier per K-tile (R12 structure), deeper prefetch (4 tiles ahead).
// mode 0: raw -> fp16   1: sigmoid(acc+bias) -> fp16   3: acc(+bias)+resid -> fp32
#define NSTG  5
#define ASTH  40
#define AWRDH (128 * ASTH)
#define BWRDH (256 * ASTH)
#define STGH  (AWRDH + BWRDH)
#define GSMEM (NSTG * STGH * 2)     // 153600 bytes

struct GB { const __half* Bt; const float* bias; const float* resid; void* C; int mode; };
struct GArgs { GB g[4]; };

__global__ __launch_bounds__(512, 1) void gemm_mma(const __half* __restrict__ A,
                                                   GArgs ga, int K, int N) {
    extern __shared__ char smem[];
    uint32_t sbase = smem_u32(smem);

    GB gb = ga.g[blockIdx.z];
    const __half* __restrict__ Bt = gb.Bt;

    int tid = threadIdx.x;
    int wid = tid >> 5, lane = tid & 31;
    int wm = wid & 3, wn = wid >> 2;
    int m0 = wm * 32, n0 = wn * 64;
    int grp = lane >> 2, ktid = lane & 3;
    int brow = blockIdx.y * 128, bcol = blockIdx.x * 256;

    int arow = tid >> 2, ach = tid & 3;
    const __half* gA = A + (size_t)(brow + arow) * K + ach * 8;
    uint32_t dA = sbase + (uint32_t)(arow * ASTH + ach * 8) * 2;
    int brw = tid >> 1, bch = tid & 1;
    const __half* gB = Bt + (size_t)(bcol + brw) * K + bch * 16;
    uint32_t dB = sbase + (uint32_t)(AWRDH + brw * ASTH + bch * 16) * 2;

    int l7 = lane & 7;
    int aq = (lane >> 3) & 1, ah = lane >> 4;
    int bq = lane >> 4, bh = (lane >> 3) & 1;
    uint32_t aB = sbase + (uint32_t)((m0 + aq * 8 + l7) * ASTH) * 2 + (uint32_t)(ah * 16);
    uint32_t bB = sbase + (uint32_t)(AWRDH + (n0 + bq * 8 + l7) * ASTH) * 2 + (uint32_t)(bh * 16);

    float acc[2][8][4];
#pragma unroll
    for (int i = 0; i < 2; i++)
#pragma unroll
        for (int j = 0; j < 8; j++)
#pragma unroll
            for (int v = 0; v < 4; v++) acc[i][j][v] = 0.f;

    const int nk = K / 32;

    // prologue: fill NSTG-1 = 4 stages
#pragma unroll
    for (int p = 0; p < NSTG - 1; p++) {
        uint32_t o = (uint32_t)p * (STGH * 2);
        CP_ASYNC16(dA + o, gA + p * 32);
        CP_ASYNC16(dB + o, gB + p * 32);
        CP_ASYNC16(dB + o + 16, gB + p * 32 + 8);
        CP_COMMIT();
    }

    int cslot = 0;           // slot of tile kt
    int wslot = NSTG - 1;    // slot of tile kt+NSTG-1 (being filled)
    for (int kt = 0; kt < nk; kt++) {
        CP_WAIT3();
        __syncthreads();

        if (kt + NSTG - 1 < nk) {
            uint32_t o = (uint32_t)wslot * (STGH * 2);
            const __half* a = gA + (kt + NSTG - 1) * 32;
            const __half* b = gB + (kt + NSTG - 1) * 32;
            CP_ASYNC16(dA + o, a);
            CP_ASYNC16(dB + o, b);
            CP_ASYNC16(dB + o + 16, b + 8);
        }
        CP_COMMIT();

        uint32_t so = (uint32_t)cslot * (STGH * 2);

#pragma unroll
        for (int ks = 0; ks < 2; ks++) {
            uint32_t af[2][4], bf[8][2];
#pragma unroll
            for (int mi = 0; mi < 2; mi++)
                LDSM4(af[mi][0], af[mi][1], af[mi][2], af[mi][3],
                      aB + so + (uint32_t)(mi * 16 * ASTH * 2) + (uint32_t)(ks * 32));
#pragma unroll
            for (int p = 0; p < 4; p++)
                LDSM4(bf[2 * p][0], bf[2 * p][1], bf[2 * p + 1][0], bf[2 * p + 1][1],
                      bB + so + (uint32_t)(p * 16 * ASTH * 2) + (uint32_t)(ks * 32));
#pragma unroll
            for (int mi = 0; mi < 2; mi++)
#pragma unroll
                for (int ni = 0; ni < 8; ni++)
                    MMA_F16(acc[mi][ni], af[mi], bf[ni]);
        }

        cslot++; if (cslot == NSTG) cslot = 0;
        wslot++; if (wslot == NSTG) wslot = 0;
    }

    // ---------------- epilogue ----------------
    int mode = gb.mode;
    const float* bias = gb.bias;
    const float* resid = gb.resid;
#pragma unroll
    for (int mi = 0; mi < 2; mi++) {
#pragma unroll
        for (int ni = 0; ni < 8; ni++) {
            int row = brow + m0 + mi * 16 + grp;
            int col = bcol + n0 + ni * 8 + ktid * 2;
            float b0v = 0.f, b1v = 0.f;
            if ((mode != 0) && bias) { b0v = bias[col]; b1v = bias[col + 1]; }
#pragma unroll
            for (int half = 0; half < 2; half++) {
                int r = row + half * 8;
                float v0 = acc[mi][ni][half * 2 + 0] + b0v;
                float v1 = acc[mi][ni][half * 2 + 1] + b1v;
                size_t off = (size_t)r * N + col;
                if (mode == 3) {
                    float2 rr = *(const float2*)(resid + off);
                    float2 o; o.x = v0 + rr.x; o.y = v1 + rr.y;
                    *(float2*)((float*)gb.C + off) = o;
                } else {
                    if (mode == 1) { v0 = sigm(v0); v1 = sigm(v1); }
                    uint32_t pk = pack_h2(v0, v1);
                    *(uint32_t*)((__half*)gb.C + off) = pk;
                }
            }
        }
    }
}

// ---------------- zi = fp16(b0 * b1) elementwise (half in/out) ----------------
__global__ __launch_bounds__(256) void gateprod(const __half2* __restrict__ b0,
                                                const __half2* __restrict__ b1,
                                                __half2* __restrict__ o) {
    int i = blockIdx.x * 256 + threadIdx.x;
    uint2 pa = ((const uint2*)b0)[i];
    uint2 pb = ((const uint2*)b1)[i];
    float2 a0 = __half22float2(*(__half2*)&pa.x), a1 = __half22float2(*(__half2*)&pa.y);
    float2 c0 = __half22float2(*(__half2*)&pb.x), c1 = __half22float2(*(__half2*)&pb.y);
    uint2 pk;
    pk.x = pack_h2(a0.x * c0.x, a0.y * c0.y);
    pk.y = pack_h2(a1.x * c1.x, a1.y * c1.y);
    ((uint2*)o)[i] = pk;
}

// ---------------- chunked scan: h_t = r_t*h_{t-1} + yi_t,  yi = b0*b1 (half inputs) ----------------
__global__ __launch_bounds__(256) void scan_pass1(const __half* __restrict__ b0,
                                                  const __half* __restrict__ b1,
                                                  const __half* __restrict__ rb,
                                                  float* __restrict__ Ac,
                                                  float* __restrict__ Sc) {
    int idx = blockIdx.x * 256 + threadIdx.x;
    int ch  = idx & 8191;
    int c   = idx >> 13;
    int b   = ch >> 11;
    int base = (b * 2048 + c * TCH) * 2048 + (ch & 2047);
    float A = 1.f, S = 0.f;
#pragma unroll 4
    for (int t = 0; t < TCH; t++) {
        float rr = __half2float(rb[base]);
        float yi = __half2float(b0[base]) * __half2float(b1[base]);
        S = fmaf(rr, S, yi);
        A *= rr;
        base += 2048;
    }
    Ac[idx] = A;
    Sc[idx] = S;
}

__global__ __launch_bounds__(256) void scan_pass2(const float* __restrict__ mem,
                                                  const float* __restrict__ Ac,
                                                  const float* __restrict__ Sc,
                                                  float* __restrict__ Hc,
                                                  float* __restrict__ memout) {
    int ch = blockIdx.x * 256 + threadIdx.x;
    float h = mem[ch];
#pragma unroll
    for (int c = 0; c < NCHUNK; c++) {
        int i = c * 8192 + ch;
        Hc[i] = h;
        h = fmaf(Ac[i], h, Sc[i]);
    }
    memout[ch] = h;
}

__global__ __launch_bounds__(256) void scan_pass3(const __half* __restrict__ b0,
                                                  const __half* __restrict__ b1,
                                                  const __half* __restrict__ rb,
                                                  const __half* __restrict__ og,
                                                  const float* __restrict__ Hc,
                                                  __half* __restrict__ g) {
    int idx = blockIdx.x * 256 + threadIdx.x;
    int ch  = idx & 8191;
    int c   = idx >> 13;
    int b   = ch >> 11;
    int base = (b * 2048 + c * TCH) * 2048 + (ch & 2047);
    float h = Hc[idx];
#pragma unroll 4
    for (int t = 0; t < TCH; t++) {
        float rr = __half2float(rb[base]);
        float yi = __half2float(b0[base]) * __half2float(b1[base]);
        h = fmaf(rr, h, yi);
        float s = h / (1.f + fabsf(h));
        g[base] = __float2half_rn(s * __half2float(og[base]));
        base += 2048;
    }
}

// ---------------- host launch ----------------
extern "C" void kernel_launch(void* const* d_in, const int* in_sizes, int n_in,
                              void* d_out, int out_size) {
    const float* x    = (const float*)d_in[0];
    const float* mem  = (const float*)d_in[1];
    const float* ln1w = (const float*)d_in[2];
    const float* ln1b = (const float*)d_in[3];
    const float* wf   = (const float*)d_in[4];
    const float* wfb  = (const float*)d_in[5];
    const float* wi   = (const float*)d_in[6];
    const float* wig  = (const float*)d_in[7];
    const float* wigb = (const float*)d_in[8];
    const float* wog  = (const float*)d_in[9];
    const float* wogb = (const float*)d_in[10];
    const float* wo   = (const float*)d_in[11];
    const float* ln2w = (const float*)d_in[12];
    const float* ln2b = (const float*)d_in[13];
    const float* fwi  = (const float*)d_in[14];
    const float* fwg  = (const float*)d_in[15];
    const float* fwgb = (const float*)d_in[16];
    const float* fwo  = (const float*)d_in[17];
    const float* fwob = (const float*)d_in[18];
    float* out = (float*)d_out;

    float *x2, *Ac, *Sc, *Hc;
    __half *wH, *yh, *zh, *gh, *zi, *b0h, *b1h, *rbh, *ogh;
    cudaGetSymbolAddress((void**)&x2, g_x2);
    cudaGetSymbolAddress((void**)&Ac, g_Ac);
    cudaGetSymbolAddress((void**)&Sc, g_Sc);
    cudaGetSymbolAddress((void**)&Hc, g_Hc);
    cudaGetSymbolAddress((void**)&wH, g_wH);
    cudaGetSymbolAddress((void**)&yh, g_yh);
    cudaGetSymbolAddress((void**)&zh, g_zh);
    cudaGetSymbolAddress((void**)&gh, g_gh);
    cudaGetSymbolAddress((void**)&zi, g_zi);
    cudaGetSymbolAddress((void**)&b0h, g_b0);
    cudaGetSymbolAddress((void**)&b1h, g_b1);
    cudaGetSymbolAddress((void**)&rbh, g_r);
    cudaGetSymbolAddress((void**)&ogh, g_og);

    cudaFuncSetAttribute(gemm_mma, cudaFuncAttributeMaxDynamicSharedMemorySize, GSMEM);

    __half* wiT  = wH + 0 * WSLOT;
    __half* wigT = wH + 1 * WSLOT;
    __half* wfT  = wH + 2 * WSLOT;
    __half* wogT = wH + 3 * WSLOT;
    __half* woT  = wH + 4 * WSLOT;
    __half* fwiT = wH + 5 * WSLOT;
    __half* fwgT = wH + 6 * WSLOT;
    __half* fwoT = wH + 7 * WSLOT;

    TArgs ta;
    ta.s[0] = wi;  ta.d[0] = wiT;  ta.K[0] = E_DIM; ta.N[0] = M_DIM;
    ta.s[1] = wig; ta.d[1] = wigT; ta.K[1] = E_DIM; ta.N[1] = M_DIM;
    ta.s[2] = wf;  ta.d[2] = wfT;  ta.K[2] = E_DIM; ta.N[2] = M_DIM;
    ta.s[3] = wog; ta.d[3] = wogT; ta.K[3] = E_DIM; ta.N[3] = M_DIM;
    ta.s[4] = wo;  ta.d[4] = woT;  ta.K[4] = M_DIM; ta.N[4] = E_DIM;
    ta.s[5] = fwi; ta.d[5] = fwiT; ta.K[5] = E_DIM; ta.N[5] = M_DIM;
    ta.s[6] = fwg; ta.d[6] = fwgT; ta.K[6] = E_DIM; ta.N[6] = M_DIM;
    ta.s[7] = fwo; ta.d[7] = fwoT; ta.K[7] = M_DIM; ta.N[7] = E_DIM;
    dim3 tg(WSLOT / (32 * 32), 8);
    tcvt8<<<tg, dim3(32, 8)>>>(ta);

    ln1024<<<R_ROWS, 256>>>(x, ln1w, ln1b, yh);

    // 4 gate GEMMs in one launch (fp16 outputs)
    {
        GArgs ga;
        ga.g[0] = { wiT,  nullptr, nullptr, b0h, 0 };
        ga.g[1] = { wigT, wigb,    nullptr, b1h, 1 };
        ga.g[2] = { wfT,  wfb,     nullptr, rbh, 1 };
        ga.g[3] = { wogT, wogb,    nullptr, ogh, 1 };
        dim3 gr(M_DIM / 256, R_ROWS / 128, 4);
        gemm_mma<<<gr, 512, GSMEM>>>(yh, ga, E_DIM, M_DIM);
    }

    scan_pass1<<<NCHUNK * 8192 / 256, 256>>>(b0h, b1h, rbh, Ac, Sc);
    scan_pass2<<<8192 / 256, 256>>>(mem, Ac, Sc, Hc, out + (size_t)R_ROWS * E_DIM);
    scan_pass3<<<NCHUNK * 8192 / 256, 256>>>(b0h, b1h, rbh, ogh, Hc, gh);

    // x2 = x + g @ wo
    {
        GArgs ga;
        ga.g[0] = { woT, nullptr, x, x2, 3 };
        dim3 gr(E_DIM / 256, R_ROWS / 128, 1);
        gemm_mma<<<gr, 512, GSMEM>>>(gh, ga, M_DIM, E_DIM);
    }

    ln1024<<<R_ROWS, 256>>>(x2, ln2w, ln2b, zh);

    // FFN in+gate in one launch (fp16 outputs)
    {
        GArgs ga;
        ga.g[0] = { fwiT, nullptr, nullptr, b0h, 0 };
        ga.g[1] = { fwgT, fwgb,    nullptr, b1h, 1 };
        dim3 gr(M_DIM / 256, R_ROWS / 128, 2);
        gemm_mma<<<gr, 512, GSMEM>>>(zh, ga, E_DIM, M_DIM);
    }

    // zi = fp16(b0*b1)
    gateprod<<<R_ROWS * M_DIM / 4 / 256, 256>>>((const __half2*)b0h, (const __half2*)b1h, (__half2*)zi);

    // out = x2 + zi @ fwo + fwob
    {
        GArgs ga;
        ga.g[0] = { fwoT, fwob, x2, out, 3 };
        dim3 gr(E_DIM / 256, R_ROWS / 128, 1);
        gemm_mma<<<gr, 512, GSMEM>>>(zi, ga, M_DIM, E_DIM);
    }
}

// round 15
// speedup vs baseline: 1.1233x; 1.0895x over previous
#include <cuda_runtime.h>
#include <cuda_fp16.h>
#include <cstdint>
#include <math.h>

// Sizes fixed: B=4, T=2048, E=1024, M=2048; R = B*T = 8192.
#define R_ROWS 8192
#define E_DIM  1024
#define M_DIM  2048
#define NCHUNK 32
#define TCH    64

// ---------------- scratch ----------------
__device__ float g_x2[R_ROWS * E_DIM];
__device__ float g_Ac[NCHUNK * 8192];
__device__ float g_Sc[NCHUNK * 8192];
__device__ float g_Hc[NCHUNK * 8192];
#define WSLOT (E_DIM * M_DIM)
__device__ __align__(256) __half g_wH[8 * WSLOT];      // transposed fp16 weights [N][K]
__device__ __align__(256) __half g_yh[R_ROWS * E_DIM]; // LN1 out
__device__ __align__(256) __half g_zh[R_ROWS * E_DIM]; // LN2 out
__device__ __align__(256) __half g_gh[R_ROWS * M_DIM]; // gate out
__device__ __align__(256) __half g_zi[R_ROWS * M_DIM]; // FFN gated product
__device__ __align__(256) __half g_b0[R_ROWS * M_DIM];
__device__ __align__(256) __half g_b1[R_ROWS * M_DIM];
__device__ __align__(256) __half g_r [R_ROWS * M_DIM];
__device__ __align__(256) __half g_og[R_ROWS * M_DIM];

__device__ __forceinline__ float sigm(float x) { return 1.f / (1.f + __expf(-x)); }

__device__ __forceinline__ uint32_t smem_u32(const void* p) {
    uint32_t a;
    asm("{ .reg .u64 t; cvta.to.shared.u64 t, %1; cvt.u32.u64 %0, t; }" : "=r"(a) : "l"(p));
    return a;
}

#define CP_ASYNC16(dst, src) asm volatile("cp.async.cg.shared.global [%0], [%1], 16;" :: "r"(dst), "l"(src))
#define CP_COMMIT()          asm volatile("cp.async.commit_group;" ::: "memory")
#define CP_WAIT2()           asm volatile("cp.async.wait_group 2;" ::: "memory")

#define LDSM4(r0, r1, r2, r3, addr)                                            \
    asm volatile("ldmatrix.sync.aligned.m8n8.x4.shared.b16 {%0,%1,%2,%3}, [%4];" \
        : "=r"(r0), "=r"(r1), "=r"(r2), "=r"(r3) : "r"(addr))

#define MMA_F16(c, a, b)                                                       \
    asm volatile("mma.sync.aligned.m16n8k16.row.col.f32.f16.f16.f32 "          \
        "{%0,%1,%2,%3}, {%4,%5,%6,%7}, {%8,%9}, {%0,%1,%2,%3};"                \
        : "+f"((c)[0]), "+f"((c)[1]), "+f"((c)[2]), "+f"((c)[3])               \
        : "r"((a)[0]), "r"((a)[1]), "r"((a)[2]), "r"((a)[3]),                  \
          "r"((b)[0]), "r"((b)[1]))

__device__ __forceinline__ uint32_t pack_h2(float a, float b) {
    __half2 h = __floats2half2_rn(a, b);
    return *reinterpret_cast<uint32_t*>(&h);
}

// ---------------- LayerNorm body (rows of 1024), fp16 output ----------------
__device__ __forceinline__ void ln_body(const float* __restrict__ x,
                                        const float* __restrict__ w,
                                        const float* __restrict__ b,
                                        __half* __restrict__ y,
                                        int row, float* sh) {
    const float4* xr = (const float4*)(x + (size_t)row * 1024);
    float4 v = xr[threadIdx.x];
    float s = v.x + v.y + v.z + v.w;
    float q = v.x * v.x + v.y * v.y + v.z * v.z + v.w * v.w;
#pragma unroll
    for (int o = 16; o; o >>= 1) {
        s += __shfl_xor_sync(0xFFFFFFFF, s, o);
        q += __shfl_xor_sync(0xFFFFFFFF, q, o);
    }
    int wid = threadIdx.x >> 5, lane = threadIdx.x & 31;
    if (lane == 0) { sh[wid] = s; sh[8 + wid] = q; }
    __syncthreads();
    s = 0.f; q = 0.f;
#pragma unroll
    for (int i = 0; i < 8; i++) { s += sh[i]; q += sh[8 + i]; }
    float mu  = s * (1.f / 1024.f);
    float var = q * (1.f / 1024.f) - mu * mu;
    float inv = rsqrtf(var + 1e-5f);
    float4 wv = ((const float4*)w)[threadIdx.x];
    float4 bv = ((const float4*)b)[threadIdx.x];
    uint2 pk;
    pk.x = pack_h2((v.x - mu) * inv * wv.x + bv.x, (v.y - mu) * inv * wv.y + bv.y);
    pk.y = pack_h2((v.z - mu) * inv * wv.z + bv.z, (v.w - mu) * inv * wv.w + bv.w);
    ((uint2*)(y + (size_t)row * 1024))[threadIdx.x] = pk;
}

__global__ __launch_bounds__(256) void ln1024(const float* __restrict__ x,
                                              const float* __restrict__ w,
                                              const float* __restrict__ b,
                                              __half* __restrict__ y) {
    __shared__ float sh[16];
    ln_body(x, w, b, y, blockIdx.x, sh);
}

// ---------------- merged prep: LN1 (blocks 0..8191) + 8 weight transposes ----------------
struct TArgs { const float* s[8]; __half* d[8]; int K[8]; int N[8]; };
__global__ __launch_bounds__(256) void prep(const float* __restrict__ x,
                                            const float* __restrict__ ln1w,
                                            const float* __restrict__ ln1b,
                                            __half* __restrict__ y, TArgs a) {
    __shared__ float t[32 * 33];
    int bx = blockIdx.x;
    if (bx < R_ROWS) {
        ln_body(x, ln1w, ln1b, y, bx, t);
        return;
    }
    int tb = bx - R_ROWS;           // 0..16383
    int w  = tb >> 11;              // 8 weights x 2048 tiles
    int blk = tb & 2047;
    int K = a.K[w], N = a.N[w];
    int nb = N >> 5;
    int bxx = (blk % nb) * 32;
    int by  = (blk / nb) * 32;
    const float* src = a.s[w];
    __half* dst = a.d[w];
    int tx = threadIdx.x & 31, ty = threadIdx.x >> 5;
#pragma unroll
    for (int i = ty; i < 32; i += 8)
        t[i * 33 + tx] = src[(size_t)(by + i) * N + bxx + tx];
    __syncthreads();
#pragma unroll
    for (int i = ty; i < 32; i += 8)
        dst[(size_t)(bxx + i) * K + by + tx] = __float2half_rn(t[tx * 33 + i]);
}

// ---------------- fp16 mma GEMM: CTA 128x256, BK=32(halves), 4 stages (R12) ----------------
// mode 0: raw -> fp16   1: sigmoid(acc+bias) -> fp16   3: acc(+bias)+resid -> fp32
#define NSTG  4
#define ASTH  40
#define AWRDH (128 * ASTH)
#define BWRDH (256 * ASTH)
#define STGH  (AWRDH + BWRDH)
#define GSMEM (NSTG * STGH * 2)     // 122880 bytes

struct GB { const __half* Bt; const float* bias; const float* resid; void* C; int mode; };
struct GArgs { GB g[4]; };

__global__ __launch_bounds__(512, 1) void gemm_mma(const __half* __restrict__ A,
                                                   GArgs ga, int K, int N) {
    extern __shared__ char smem[];
    uint32_t sbase = smem_u32(smem);

    GB gb = ga.g[blockIdx.z];
    const __half* __restrict__ Bt = gb.Bt;

    int tid = threadIdx.x;
    int wid = tid >> 5, lane = tid & 31;
    int wm = wid & 3, wn = wid >> 2;
    int m0 = wm * 32, n0 = wn * 64;
    int grp = lane >> 2, ktid = lane & 3;
    int brow = blockIdx.y * 128, bcol = blockIdx.x * 256;

    int arow = tid >> 2, ach = tid & 3;
    const __half* gA = A + (size_t)(brow + arow) * K + ach * 8;
    uint32_t dA = sbase + (uint32_t)(arow * ASTH + ach * 8) * 2;
    int brw = tid >> 1, bch = tid & 1;
    const __half* gB = Bt + (size_t)(bcol + brw) * K + bch * 16;
    uint32_t dB = sbase + (uint32_t)(AWRDH + brw * ASTH + bch * 16) * 2;

    int l7 = lane & 7;
    int aq = (lane >> 3) & 1, ah = lane >> 4;
    int bq = lane >> 4, bh = (lane >> 3) & 1;
    uint32_t aB = sbase + (uint32_t)((m0 + aq * 8 + l7) * ASTH) * 2 + (uint32_t)(ah * 16);
    uint32_t bB = sbase + (uint32_t)(AWRDH + (n0 + bq * 8 + l7) * ASTH) * 2 + (uint32_t)(bh * 16);

    float acc[2][8][4];
#pragma unroll
    for (int i = 0; i < 2; i++)
#pragma unroll
        for (int j = 0; j < 8; j++)
#pragma unroll
            for (int v = 0; v < 4; v++) acc[i][j][v] = 0.f;

    const int nk = K / 32;

#pragma unroll
    for (int p = 0; p < NSTG - 1; p++) {
        uint32_t o = (uint32_t)p * (STGH * 2);
        CP_ASYNC16(dA + o, gA + p * 32);
        CP_ASYNC16(dB + o, gB + p * 32);
        CP_ASYNC16(dB + o + 16, gB + p * 32 + 8);
        CP_COMMIT();
    }

    for (int kt = 0; kt < nk; kt++) {
        CP_WAIT2();
        __syncthreads();

        if (kt + NSTG - 1 < nk) {
            uint32_t o = (uint32_t)((kt + NSTG - 1) & (NSTG - 1)) * (STGH * 2);
            const __half* a = gA + (kt + NSTG - 1) * 32;
            const __half* b = gB + (kt + NSTG - 1) * 32;
            CP_ASYNC16(dA + o, a);
            CP_ASYNC16(dB + o, b);
            CP_ASYNC16(dB + o + 16, b + 8);
        }
        CP_COMMIT();

        uint32_t so = (uint32_t)(kt & (NSTG - 1)) * (STGH * 2);

#pragma unroll
        for (int ks = 0; ks < 2; ks++) {
            uint32_t af[2][4], bf[8][2];
#pragma unroll
            for (int mi = 0; mi < 2; mi++)
                LDSM4(af[mi][0], af[mi][1], af[mi][2], af[mi][3],
                      aB + so + (uint32_t)(mi * 16 * ASTH * 2) + (uint32_t)(ks * 32));
#pragma unroll
            for (int p = 0; p < 4; p++)
                LDSM4(bf[2 * p][0], bf[2 * p][1], bf[2 * p + 1][0], bf[2 * p + 1][1],
                      bB + so + (uint32_t)(p * 16 * ASTH * 2) + (uint32_t)(ks * 32));
#pragma unroll
            for (int mi = 0; mi < 2; mi++)
#pragma unroll
                for (int ni = 0; ni < 8; ni++)
                    MMA_F16(acc[mi][ni], af[mi], bf[ni]);
        }
    }

    // ---------------- epilogue ----------------
    int mode = gb.mode;
    const float* bias = gb.bias;
    const float* resid = gb.resid;
#pragma unroll
    for (int mi = 0; mi < 2; mi++) {
#pragma unroll
        for (int ni = 0; ni < 8; ni++) {
            int row = brow + m0 + mi * 16 + grp;
            int col = bcol + n0 + ni * 8 + ktid * 2;
            float b0v = 0.f, b1v = 0.f;
            if ((mode != 0) && bias) { b0v = bias[col]; b1v = bias[col + 1]; }
#pragma unroll
            for (int half = 0; half < 2; half++) {
                int r = row + half * 8;
                float v0 = acc[mi][ni][half * 2 + 0] + b0v;
                float v1 = acc[mi][ni][half * 2 + 1] + b1v;
                size_t off = (size_t)r * N + col;
                if (mode == 3) {
                    float2 rr = *(const float2*)(resid + off);
                    float2 o; o.x = v0 + rr.x; o.y = v1 + rr.y;
                    *(float2*)((float*)gb.C + off) = o;
                } else {
                    if (mode == 1) { v0 = sigm(v0); v1 = sigm(v1); }
                    uint32_t pk = pack_h2(v0, v1);
                    *(uint32_t*)((__half*)gb.C + off) = pk;
                }
            }
        }
    }
}

// ---------------- zi = fp16(b0 * b1) elementwise (half in/out) ----------------
__global__ __launch_bounds__(256) void gateprod(const __half2* __restrict__ b0,
                                                const __half2* __restrict__ b1,
                                                __half2* __restrict__ o) {
    int i = blockIdx.x * 256 + threadIdx.x;
    uint2 pa = ((const uint2*)b0)[i];
    uint2 pb = ((const uint2*)b1)[i];
    float2 a0 = __half22float2(*(__half2*)&pa.x), a1 = __half22float2(*(__half2*)&pa.y);
    float2 c0 = __half22float2(*(__half2*)&pb.x), c1 = __half22float2(*(__half2*)&pb.y);
    uint2 pk;
    pk.x = pack_h2(a0.x * c0.x, a0.y * c0.y);
    pk.y = pack_h2(a1.x * c1.x, a1.y * c1.y);
    ((uint2*)o)[i] = pk;
}

// ---------------- chunked scan: h_t = r_t*h_{t-1} + yi_t,  yi = b0*b1 ----------------
__global__ __launch_bounds__(256) void scan_pass1(const __half* __restrict__ b0,
                                                  const __half* __restrict__ b1,
                                                  const __half* __restrict__ rb,
                                                  float* __restrict__ Ac,
                                                  float* __restrict__ Sc) {
    int idx = blockIdx.x * 256 + threadIdx.x;   // c*8192 + ch
    int ch  = idx & 8191;
    int c   = idx >> 13;
    int b   = ch >> 11;
    int base = (b * 2048 + c * TCH) * 2048 + (ch & 2047);
    float A = 1.f, S = 0.f;
#pragma unroll 4
    for (int t = 0; t < TCH; t++) {
        float rr = __half2float(rb[base]);
        float yi = __half2float(b0[base]) * __half2float(b1[base]);
        S = fmaf(rr, S, yi);
        A *= rr;
        base += 2048;
    }
    Ac[idx] = A;
    Sc[idx] = S;
}

__global__ __launch_bounds__(256) void scan_pass2(const float* __restrict__ mem,
                                                  const float* __restrict__ Ac,
                                                  const float* __restrict__ Sc,
                                                  float* __restrict__ Hc,
                                                  float* __restrict__ memout) {
    int ch = blockIdx.x * 256 + threadIdx.x;
    float h = mem[ch];
#pragma unroll
    for (int c = 0; c < NCHUNK; c++) {
        int i = c * 8192 + ch;
        Hc[i] = h;
        h = fmaf(Ac[i], h, Sc[i]);
    }
    memout[ch] = h;
}

__global__ __launch_bounds__(256) void scan_pass3(const __half* __restrict__ b0,
                                                  const __half* __restrict__ b1,
                                                  const __half* __restrict__ rb,
                                                  const __half* __restrict__ og,
                                                  const float* __restrict__ Hc,
                                                  __half* __restrict__ g) {
    int idx = blockIdx.x * 256 + threadIdx.x;
    int ch  = idx & 8191;
    int c   = idx >> 13;
    int b   = ch >> 11;
    int base = (b * 2048 + c * TCH) * 2048 + (ch & 2047);
    float h = Hc[idx];
#pragma unroll 4
    for (int t = 0; t < TCH; t++) {
        float rr = __half2float(rb[base]);
        float yi = __half2float(b0[base]) * __half2float(b1[base]);
        h = fmaf(rr, h, yi);
        float s = h / (1.f + fabsf(h));
        g[base] = __float2half_rn(s * __half2float(og[base]));
        base += 2048;
    }
}

// ---------------- host launch ----------------
extern "C" void kernel_launch(void* const* d_in, const int* in_sizes, int n_in,
                              void* d_out, int out_size) {
    const float* x    = (const float*)d_in[0];
    const float* mem  = (const float*)d_in[1];
    const float* ln1w = (const float*)d_in[2];
    const float* ln1b = (const float*)d_in[3];
    const float* wf   = (const float*)d_in[4];
    const float* wfb  = (const float*)d_in[5];
    const float* wi   = (const float*)d_in[6];
    const float* wig  = (const float*)d_in[7];
    const float* wigb = (const float*)d_in[8];
    const float* wog  = (const float*)d_in[9];
    const float* wogb = (const float*)d_in[10];
    const float* wo   = (const float*)d_in[11];
    const float* ln2w = (const float*)d_in[12];
    const float* ln2b = (const float*)d_in[13];
    const float* fwi  = (const float*)d_in[14];
    const float* fwg  = (const float*)d_in[15];
    const float* fwgb = (const float*)d_in[16];
    const float* fwo  = (const float*)d_in[17];
    const float* fwob = (const float*)d_in[18];
    float* out = (float*)d_out;

    float *x2, *Ac, *Sc, *Hc;
    __half *wH, *yh, *zh, *gh, *zi, *b0h, *b1h, *rbh, *ogh;
    cudaGetSymbolAddress((void**)&x2, g_x2);
    cudaGetSymbolAddress((void**)&Ac, g_Ac);
    cudaGetSymbolAddress((void**)&Sc, g_Sc);
    cudaGetSymbolAddress((void**)&Hc, g_Hc);
    cudaGetSymbolAddress((void**)&wH, g_wH);
    cudaGetSymbolAddress((void**)&yh, g_yh);
    cudaGetSymbolAddress((void**)&zh, g_zh);
    cudaGetSymbolAddress((void**)&gh, g_gh);
    cudaGetSymbolAddress((void**)&zi, g_zi);
    cudaGetSymbolAddress((void**)&b0h, g_b0);
    cudaGetSymbolAddress((void**)&b1h, g_b1);
    cudaGetSymbolAddress((void**)&rbh, g_r);
    cudaGetSymbolAddress((void**)&ogh, g_og);

    cudaFuncSetAttribute(gemm_mma, cudaFuncAttributeMaxDynamicSharedMemorySize, GSMEM);

    __half* wiT  = wH + 0 * WSLOT;
    __half* wigT = wH + 1 * WSLOT;
    __half* wfT  = wH + 2 * WSLOT;
    __half* wogT = wH + 3 * WSLOT;
    __half* woT  = wH + 4 * WSLOT;
    __half* fwiT = wH + 5 * WSLOT;
    __half* fwgT = wH + 6 * WSLOT;
    __half* fwoT = wH + 7 * WSLOT;

    TArgs ta;
    ta.s[0] = wi;  ta.d[0] = wiT;  ta.K[0] = E_DIM; ta.N[0] = M_DIM;
    ta.s[1] = wig; ta.d[1] = wigT; ta.K[1] = E_DIM; ta.N[1] = M_DIM;
    ta.s[2] = wf;  ta.d[2] = wfT;  ta.K[2] = E_DIM; ta.N[2] = M_DIM;
    ta.s[3] = wog; ta.d[3] = wogT; ta.K[3] = E_DIM; ta.N[3] = M_DIM;
    ta.s[4] = wo;  ta.d[4] = woT;  ta.K[4] = M_DIM; ta.N[4] = E_DIM;
    ta.s[5] = fwi; ta.d[5] = fwiT; ta.K[5] = E_DIM; ta.N[5] = M_DIM;
    ta.s[6] = fwg; ta.d[6] = fwgT; ta.K[6] = E_DIM; ta.N[6] = M_DIM;
    ta.s[7] = fwo; ta.d[7] = fwoT; ta.K[7] = M_DIM; ta.N[7] = E_DIM;

    // merged LN1 + all weight transposes
    prep<<<R_ROWS + 8 * 2048, 256>>>(x, ln1w, ln1b, yh, ta);

    // 4 gate GEMMs in one launch (fp16 outputs)
    {
        GArgs ga;
        ga.g[0] = { wiT,  nullptr, nullptr, b0h, 0 };
        ga.g[1] = { wigT, wigb,    nullptr, b1h, 1 };
        ga.g[2] = { wfT,  wfb,     nullptr, rbh, 1 };
        ga.g[3] = { wogT, wogb,    nullptr, ogh, 1 };
        dim3 gr(M_DIM / 256, R_ROWS / 128, 4);
        gemm_mma<<<gr, 512, GSMEM>>>(yh, ga, E_DIM, M_DIM);
    }

    scan_pass1<<<NCHUNK * 8192 / 256, 256>>>(b0h, b1h, rbh, Ac, Sc);
    scan_pass2<<<8192 / 256, 256>>>(mem, Ac, Sc, Hc, out + (size_t)R_ROWS * E_DIM);
    scan_pass3<<<NCHUNK * 8192 / 256, 256>>>(b0h, b1h, rbh, ogh, Hc, gh);

    // x2 = x + g @ wo
    {
        GArgs ga;
        ga.g[0] = { woT, nullptr, x, x2, 3 };
        dim3 gr(E_DIM / 256, R_ROWS / 128, 1);
        gemm_mma<<<gr, 512, GSMEM>>>(gh, ga, M_DIM, E_DIM);
    }

    ln1024<<<R_ROWS, 256>>>(x2, ln2w, ln2b, zh);

    // FFN in+gate in one launch (fp16 outputs)
    {
        GArgs ga;
        ga.g[0] = { fwiT, nullptr, nullptr, b0h, 0 };
        ga.g[1] = { fwgT, fwgb,    nullptr, b1h, 1 };
        dim3 gr(M_DIM / 256, R_ROWS / 128, 2);
        gemm_mma<<<gr, 512, GSMEM>>>(zh, ga, E_DIM, M_DIM);
    }

    // zi = fp16(b0*b1)
    gateprod<<<R_ROWS * M_DIM / 4 / 256, 256>>>((const __half2*)b0h, (const __half2*)b1h, (__half2*)zi);

    // out = x2 + zi @ fwo + fwob
    {
        GArgs ga;
        ga.g[0] = { fwoT, fwob, x2, out, 3 };
        dim3 gr(E_DIM / 256, R_ROWS / 128, 1);
        gemm_mma<<<gr, 512, GSMEM>>>(zi, ga, M_DIM, E_DIM);
    }
}